// round 11
// baseline (speedup 1.0000x reference)
#include <cuda_runtime.h>
#include <cuda_fp16.h>

// Problem constants (fixed by the dataset)
#define N_TOTAL   10000
#define NUM_ATOMS 100
#define N_EDGES   1000000
#define NCL 38
#define NFL 12

#define EDGE_THREADS 256
#define EPT 8                         // edges per thread, one mega-stage
#define EDGE_PER_BLOCK (EDGE_THREADS * EPT)          // 2048
#define EDGE_BLOCKS ((N_EDGES + EDGE_PER_BLOCK - 1) / EDGE_PER_BLOCK)  // 489

// Scratch (alloc-free rule: __device__ globals)
__device__ float4 g_NA[N_TOTAL];   // {x, a(i-role), b(j-role), half2(sin,cos)}

__device__ __forceinline__ float safe_inv_f(float v) {
    float w = (fabsf(v) < 0.01f) ? ((v >= 0.0f) ? 0.01f : -0.01f) : v;
    return __fdividef(1.0f, w);
}

// ---------------- node pass: F(x) -> out, plus packed per-node table ----------------
__global__ void node_kernel(const float* __restrict__ x,
                            const float* __restrict__ c_mask,
                            const float* __restrict__ f_mask,
                            const float* __restrict__ wc2,
                            const float* __restrict__ wf2,
                            float* __restrict__ out) {
    __shared__ float swc[NCL];
    __shared__ float swf[NFL];
    int t = threadIdx.x;
    if (t < NCL) swc[t] = c_mask[t] * (wc2[t] - wc2[t + NCL]);
    if (t < NFL) swf[t] = f_mask[t] * (wf2[t] - wf2[t + NFL]);
    __syncthreads();

    int n = blockIdx.x * blockDim.x + t;
    if (n >= N_TOTAL) return;
    float xv = x[n];
    float s, c;
    __sincosf(xv, &s, &c);
    float E = __expf(-xv);
    float R = __expf(xv);
    float inv  = safe_inv_f(xv);
    float inv2 = inv * inv;
    float th = (R - E) * __fdividef(1.0f, R + E);     // tanh(x)
    float sg = __fdividef(1.0f, 1.0f + E);            // sigmoid(x)
    float rl = fmaxf(xv, 0.0f);
    float x2 = xv * xv;

    float F = swf[0]
            + swf[1]*s + swf[2]*c + swf[3]*xv*s
            + swf[4]*xv + swf[5]*x2
            + swf[6]*inv + swf[7]*inv2 + swf[8]*inv2*inv
            + swf[9]*th + swf[10]*sg + swf[11]*rl;
    out[n] = F;   // F_COEF = 1; edge kernel accumulates on top

    // node-as-x_i contribution (feature idx 0,3,6,10,18,19,26,27,28)
    float a = swc[0]*xv + swc[3]*x2 + swc[6]*inv + swc[10]*inv2
            + swc[18]*s + swc[19]*c + swc[26]*th + swc[27]*sg + swc[28]*rl;
    // node-as-x_j contribution (feature idx 1,4,7,11,20,21,29,30,31)
    float b = swc[1]*xv + swc[4]*x2 + swc[7]*inv + swc[11]*inv2
            + swc[20]*s + swc[21]*c + swc[29]*th + swc[30]*sg + swc[31]*rl;

    __half2 sc = __floats2half2_rn(s, c);
    g_NA[n] = make_float4(xv, a, b, __uint_as_float(*reinterpret_cast<unsigned*>(&sc)));
}

// ---------------- edge pass: all-L1 gathers, EPT=8 mega-stage, PDL-gated ----------------
__global__ void __launch_bounds__(EDGE_THREADS, 5)
edge_kernel(const void* __restrict__ eidx_raw,
            const float* __restrict__ c_mask,
            const float* __restrict__ wc2,
            const float* __restrict__ edge_attr,
            float* __restrict__ out) {
    __shared__ float sW[NCL];
    __shared__ int   sE64;

    const int t = threadIdx.x;

    // -------- prologue: runs concurrently with node_kernel tail (PDL) --------
    if (t < NCL) sW[t] = c_mask[t] * (wc2[t] - wc2[t + NCL]);
    if (t >= 64 && t < 96) {
        int k = t - 64;
        const long long* p = (const long long*)eidx_raw;
        long long v0 = p[k];
        long long v1 = p[k + 32];
        int ok = (v0 >= 0 && v0 < N_TOTAL && v1 >= 0 && v1 < N_TOTAL) ? 1 : 0;
        unsigned m = __ballot_sync(0xFFFFFFFFu, ok);
        if (k == 0) sE64 = (m == 0xFFFFFFFFu) ? 1 : 0;
    }
    __syncthreads();

    const float wd1  = sW[2],  wd2  = sW[5];
    const float wid  = sW[8],  wis  = sW[9],  wid2 = sW[12], wis2 = sW[13];
    const float wsd  = sW[14], wcd  = sW[15], wss  = sW[16], wcs  = sW[17];
    const float wxx  = sW[22], wxsj = sW[23], wxsi = sW[24], wsdcs = sW[25];
    const float wthd = sW[32], wsgd = sW[33], wrld = sW[34];
    const float wths = sW[35], wsgs = sW[36], wrls = sW[37];
    const int e64 = sE64;

    // this thread's 8 consecutive edges: [e0, e0+8)
    const int e0 = blockIdx.x * EDGE_PER_BLOCK + t * EPT;

    // ---- load ALL 8 edge index pairs up front (latency paid once) ----
    int js[EPT], is[EPT];
    int nv = N_EDGES - e0;              // edges this thread actually owns
    if (nv <= 0) nv = 0; else if (nv > EPT) nv = EPT;

    if (nv == EPT) {                    // fast path: full, aligned vector loads
        if (e64) {
            const long long* e = (const long long*)eidx_raw;
#pragma unroll
            for (int q = 0; q < EPT / 2; q++) {
                longlong2 sp = __ldcs(reinterpret_cast<const longlong2*>(e + e0 + 2 * q));
                longlong2 dp = __ldcs(reinterpret_cast<const longlong2*>(e + N_EDGES + e0 + 2 * q));
                js[2*q] = (int)sp.x; js[2*q+1] = (int)sp.y;
                is[2*q] = (int)dp.x; is[2*q+1] = (int)dp.y;
            }
        } else {
            const int* e = (const int*)eidx_raw;
#pragma unroll
            for (int q = 0; q < EPT / 4; q++) {
                int4 sp = __ldcs(reinterpret_cast<const int4*>(e + e0 + 4 * q));
                int4 dp = __ldcs(reinterpret_cast<const int4*>(e + N_EDGES + e0 + 4 * q));
                js[4*q] = sp.x; js[4*q+1] = sp.y; js[4*q+2] = sp.z; js[4*q+3] = sp.w;
                is[4*q] = dp.x; is[4*q+1] = dp.y; is[4*q+2] = dp.z; is[4*q+3] = dp.w;
            }
        }
    } else {                            // tail block: scalar predicated loads
        if (e64) {
            const long long* e = (const long long*)eidx_raw;
#pragma unroll
            for (int q = 0; q < EPT; q++) {
                js[q] = (q < nv) ? (int)e[e0 + q] : 0;
                is[q] = (q < nv) ? (int)e[N_EDGES + e0 + q] : 0;
            }
        } else {
            const int* e = (const int*)eidx_raw;
#pragma unroll
            for (int q = 0; q < EPT; q++) {
                js[q] = (q < nv) ? e[e0 + q] : 0;
                is[q] = (q < nv) ? e[N_EDGES + e0 + q] : 0;
            }
        }
    }

    // gate: g_NA and out[] produced by node_kernel
#if __CUDA_ARCH__ >= 900
    cudaGridDependencySynchronize();
#endif

    // ---- process as 4 pairs; gathers batched per pair (pipeline-friendly) ----
#pragma unroll
    for (int pr = 0; pr < EPT / 2; pr++) {
        const int k0 = 2 * pr, k1 = 2 * pr + 1;
        if (k0 >= nv) break;
        const bool v1ok = (k1 < nv);

        const int j0 = js[k0], i0 = is[k0];
        const int j1 = v1ok ? js[k1] : j0;
        const int i1 = v1ok ? is[k1] : i0;

        float4 Nj0 = __ldg(&g_NA[j0]);
        float4 Ni0 = __ldg(&g_NA[i0]);
        float4 Nj1 = __ldg(&g_NA[j1]);
        float4 Ni1 = __ldg(&g_NA[i1]);
        float  ea0 = __ldg(&edge_attr[(j0 % NUM_ATOMS) * NUM_ATOMS + (i0 % NUM_ATOMS)]);
        float  ea1 = __ldg(&edge_attr[(j1 % NUM_ATOMS) * NUM_ATOMS + (i1 % NUM_ATOMS)]);

#pragma unroll
        for (int k = 0; k < 2; k++) {
            if (k == 1 && !v1ok) break;
            float4 Ni = k ? Ni1 : Ni0;
            float4 Nj = k ? Nj1 : Nj0;
            float  ea = k ? ea1 : ea0;
            int    ii = k ? i1  : i0;

            float xi = Ni.x, ai = Ni.y;
            float xj = Nj.x, bj = Nj.z;
            unsigned ui = __float_as_uint(Ni.w);
            unsigned uj = __float_as_uint(Nj.w);
            float2 sci = __half22float2(*reinterpret_cast<__half2*>(&ui));
            float2 scj = __half22float2(*reinterpret_cast<__half2*>(&uj));
            float si = sci.x, ci = sci.y;
            float sj = scj.x, cj = scj.y;

            float d  = xj - xi;
            float sm = xj + xi;

            // trig of d and s via angle-sum identities
            float p1 = sj * ci, p2 = cj * si, p3 = ci * cj, p4 = si * sj;
            float sind = p1 - p2, sins = p1 + p2;
            float cosd = p3 + p4, coss = p3 - p4;

            float invd = safe_inv_f(d);
            float invs = safe_inv_f(sm);

            // activations via per-edge exp; tanh(z) = 2/(1+e^{-2z}) - 1
            float vd  = __expf(-d);
            float vs  = __expf(-sm);
            float vd2 = vd * vd, vs2 = vs * vs;
            float thd = fmaf(2.0f, __frcp_rn(1.0f + vd2), -1.0f);
            float sgd = __frcp_rn(1.0f + vd);
            float ths = fmaf(2.0f, __frcp_rn(1.0f + vs2), -1.0f);
            float sgs = __frcp_rn(1.0f + vs);

            float core = ai + bj;
            core = fmaf(wd1,  d,            core);
            core = fmaf(wd2,  d * d,        core);
            core = fmaf(wid,  invd,         core);
            core = fmaf(wid2, invd * invd,  core);
            core = fmaf(wis,  invs,         core);
            core = fmaf(wis2, invs * invs,  core);
            core = fmaf(wsd,  sind,         core);
            core = fmaf(wcd,  cosd,         core);
            core = fmaf(wss,  sins,         core);
            core = fmaf(wcs,  coss,         core);
            core = fmaf(wxx,  xi * xj,      core);
            core = fmaf(wxsj, xi * sj,      core);
            core = fmaf(wxsi, xj * si,      core);
            core = fmaf(wsdcs, sind * coss, core);
            core = fmaf(wthd, thd,          core);
            core = fmaf(wsgd, sgd,          core);
            core = fmaf(wrld, fmaxf(d, 0.0f),  core);
            core = fmaf(wths, ths,          core);
            core = fmaf(wsgs, sgs,          core);
            core = fmaf(wrls, fmaxf(sm, 0.0f), core);

            atomicAdd(&out[ii], ea * core);   // segment_sum over dst
        }
    }
}

extern "C" void kernel_launch(void* const* d_in, const int* in_sizes, int n_in,
                              void* d_out, int out_size) {
    // Identify inputs by element count (robust to whether scalar `t` occupies
    // a slot). Reference order: t?, x[10000], edge_index[2000000], c_mask[38],
    // f_mask[12], wc_2[76], wf_2[24], edge_attr_all[10000].
    const float* x   = nullptr;
    const void*  ei  = nullptr;
    const float* cm  = nullptr;
    const float* fm  = nullptr;
    const float* wc2 = nullptr;
    const float* wf2 = nullptr;
    const float* ea  = nullptr;
    for (int idx = 0; idx < n_in; idx++) {
        int s = in_sizes[idx];
        if (s == 2 * N_EDGES)      ei  = d_in[idx];
        else if (s == NCL)         cm  = (const float*)d_in[idx];
        else if (s == NFL)         fm  = (const float*)d_in[idx];
        else if (s == 2 * NCL)     wc2 = (const float*)d_in[idx];
        else if (s == 2 * NFL)     wf2 = (const float*)d_in[idx];
        else if (s == N_TOTAL) {
            if (!x) x = (const float*)d_in[idx];   // x comes first
            else    ea = (const float*)d_in[idx];  // edge_attr_all second
        }
    }
    float* out = (float*)d_out;

    node_kernel<<<(N_TOTAL + 255) / 256, 256>>>(x, cm, fm, wc2, wf2, out);

    // edge_kernel with programmatic dependent launch: prologue + index loads
    // overlap node_kernel tail; cudaGridDependencySynchronize() gates g_NA/out.
    cudaLaunchConfig_t cfg = {};
    cfg.gridDim  = dim3(EDGE_BLOCKS, 1, 1);
    cfg.blockDim = dim3(EDGE_THREADS, 1, 1);
    cfg.dynamicSmemBytes = 0;
    cfg.stream = 0;
    cudaLaunchAttribute attr[1];
    attr[0].id = cudaLaunchAttributeProgrammaticStreamSerialization;
    attr[0].val.programmaticStreamSerializationAllowed = 1;
    cfg.attrs = attr;
    cfg.numAttrs = 1;
    cudaError_t err = cudaLaunchKernelEx(&cfg, edge_kernel, ei, cm, wc2,
                                         (const float*)ea, out);
    if (err != cudaSuccess) {
        // fallback: plain launch (still correct, just serialized)
        edge_kernel<<<EDGE_BLOCKS, EDGE_THREADS>>>(ei, cm, wc2, ea, out);
    }
}

// round 12
// speedup vs baseline: 1.0125x; 1.0125x over previous
#include <cuda_runtime.h>
#include <cuda_fp16.h>

// Problem constants (fixed by the dataset)
#define N_TOTAL   10000
#define NUM_ATOMS 100
#define N_EDGES   1000000
#define NCL 38
#define NFL 12

#define EDGE_BLOCKS  888          // 6 per SM
#define EDGE_THREADS 256
#define EDGE_CHUNK   1128         // 888 * 1128 = 1,001,664 >= 1e6; even
// per block: stage A covers 512 edges, stage B the rest -> exactly 2 stages + tiny C
// 1128 / (256*2) = 2.203 -> need 3 stages of 512; use 2 full + 1 partial

// Scratch (alloc-free rule: __device__ globals)
__device__ float4 g_NA[N_TOTAL];   // {x, a(i-role), b(j-role), half2(sin,cos)}

__device__ __forceinline__ float safe_inv_f(float v) {
    float w = (fabsf(v) < 0.01f) ? ((v >= 0.0f) ? 0.01f : -0.01f) : v;
    return __fdividef(1.0f, w);
}

// ---------------- node pass: F(x) -> out, plus packed per-node table ----------------
__global__ void node_kernel(const float* __restrict__ x,
                            const float* __restrict__ c_mask,
                            const float* __restrict__ f_mask,
                            const float* __restrict__ wc2,
                            const float* __restrict__ wf2,
                            float* __restrict__ out) {
    __shared__ float swc[NCL];
    __shared__ float swf[NFL];
    int t = threadIdx.x;
    if (t < NCL) swc[t] = c_mask[t] * (wc2[t] - wc2[t + NCL]);
    if (t < NFL) swf[t] = f_mask[t] * (wf2[t] - wf2[t + NFL]);
    __syncthreads();

    int n = blockIdx.x * blockDim.x + t;
    if (n >= N_TOTAL) return;
    float xv = x[n];
    float s, c;
    __sincosf(xv, &s, &c);
    float E = __expf(-xv);
    float R = __expf(xv);
    float inv  = safe_inv_f(xv);
    float inv2 = inv * inv;
    float th = (R - E) * __fdividef(1.0f, R + E);     // tanh(x)
    float sg = __fdividef(1.0f, 1.0f + E);            // sigmoid(x)
    float rl = fmaxf(xv, 0.0f);
    float x2 = xv * xv;

    float F = swf[0]
            + swf[1]*s + swf[2]*c + swf[3]*xv*s
            + swf[4]*xv + swf[5]*x2
            + swf[6]*inv + swf[7]*inv2 + swf[8]*inv2*inv
            + swf[9]*th + swf[10]*sg + swf[11]*rl;
    out[n] = F;   // F_COEF = 1; edge kernel accumulates on top

    // node-as-x_i contribution (feature idx 0,3,6,10,18,19,26,27,28)
    float a = swc[0]*xv + swc[3]*x2 + swc[6]*inv + swc[10]*inv2
            + swc[18]*s + swc[19]*c + swc[26]*th + swc[27]*sg + swc[28]*rl;
    // node-as-x_j contribution (feature idx 1,4,7,11,20,21,29,30,31)
    float b = swc[1]*xv + swc[4]*x2 + swc[7]*inv + swc[11]*inv2
            + swc[20]*s + swc[21]*c + swc[29]*th + swc[30]*sg + swc[31]*rl;

    __half2 sc = __floats2half2_rn(s, c);
    g_NA[n] = make_float4(xv, a, b, __uint_as_float(*reinterpret_cast<unsigned*>(&sc)));
}

// ---------------- edge pass: all-L1 gathers, index prefetch over PDL, 3 stages ----------------
__global__ void __launch_bounds__(EDGE_THREADS, 6)
edge_kernel(const void* __restrict__ eidx_raw,
            const float* __restrict__ c_mask,
            const float* __restrict__ wc2,
            const float* __restrict__ edge_attr,
            float* __restrict__ out) {
    __shared__ float sW[NCL];
    __shared__ int   sE64;

    const int t = threadIdx.x;

    // -------- prologue: runs concurrently with node_kernel tail (PDL) --------
    if (t < NCL) sW[t] = c_mask[t] * (wc2[t] - wc2[t + NCL]);
    if (t >= 64 && t < 96) {
        int k = t - 64;
        const long long* p = (const long long*)eidx_raw;
        long long v0 = p[k];
        long long v1 = p[k + 32];
        int ok = (v0 >= 0 && v0 < N_TOTAL && v1 >= 0 && v1 < N_TOTAL) ? 1 : 0;
        unsigned m = __ballot_sync(0xFFFFFFFFu, ok);
        if (k == 0) sE64 = (m == 0xFFFFFFFFu) ? 1 : 0;
    }
    __syncthreads();

    const float wd1  = sW[2],  wd2  = sW[5];
    const float wid  = sW[8],  wis  = sW[9],  wid2 = sW[12], wis2 = sW[13];
    const float wsd  = sW[14], wcd  = sW[15], wss  = sW[16], wcs  = sW[17];
    const float wxx  = sW[22], wxsj = sW[23], wxsi = sW[24], wsdcs = sW[25];
    const float wthd = sW[32], wsgd = sW[33], wrld = sW[34];
    const float wths = sW[35], wsgs = sW[36], wrls = sW[37];
    const int e64 = sE64;

    const int start = blockIdx.x * EDGE_CHUNK;
    const int end   = min(start + EDGE_CHUNK, N_EDGES);

    // three strided stages of 2 edges each; index loads hoisted above the PDL gate
    const int eA = start + (t << 1);
    const int eB = eA + (EDGE_THREADS << 1);
    const int eC = eB + (EDGE_THREADS << 1);
    const bool vA = (eA < end);
    const bool vB = (eB < end);
    const bool vC = (eC < end);

    int jA0=0, jA1=0, iA0=0, iA1=0;
    int jB0=0, jB1=0, iB0=0, iB1=0;
    int jC0=0, jC1=0, iC0=0, iC1=0;
    if (e64) {
        const long long* e = (const long long*)eidx_raw;
        if (vA) {
            longlong2 sp = __ldcs(reinterpret_cast<const longlong2*>(e + eA));
            longlong2 dp = __ldcs(reinterpret_cast<const longlong2*>(e + N_EDGES + eA));
            jA0 = (int)sp.x; jA1 = (int)sp.y; iA0 = (int)dp.x; iA1 = (int)dp.y;
        }
        if (vB) {
            longlong2 sp = __ldcs(reinterpret_cast<const longlong2*>(e + eB));
            longlong2 dp = __ldcs(reinterpret_cast<const longlong2*>(e + N_EDGES + eB));
            jB0 = (int)sp.x; jB1 = (int)sp.y; iB0 = (int)dp.x; iB1 = (int)dp.y;
        }
        if (vC) {
            longlong2 sp = __ldcs(reinterpret_cast<const longlong2*>(e + eC));
            longlong2 dp = __ldcs(reinterpret_cast<const longlong2*>(e + N_EDGES + eC));
            jC0 = (int)sp.x; jC1 = (int)sp.y; iC0 = (int)dp.x; iC1 = (int)dp.y;
        }
    } else {
        const int* e = (const int*)eidx_raw;
        if (vA) {
            int2 sp = __ldcs(reinterpret_cast<const int2*>(e + eA));
            int2 dp = __ldcs(reinterpret_cast<const int2*>(e + N_EDGES + eA));
            jA0 = sp.x; jA1 = sp.y; iA0 = dp.x; iA1 = dp.y;
        }
        if (vB) {
            int2 sp = __ldcs(reinterpret_cast<const int2*>(e + eB));
            int2 dp = __ldcs(reinterpret_cast<const int2*>(e + N_EDGES + eB));
            jB0 = sp.x; jB1 = sp.y; iB0 = dp.x; iB1 = dp.y;
        }
        if (vC) {
            int2 sp = __ldcs(reinterpret_cast<const int2*>(e + eC));
            int2 dp = __ldcs(reinterpret_cast<const int2*>(e + N_EDGES + eC));
            jC0 = sp.x; jC1 = sp.y; iC0 = dp.x; iC1 = dp.y;
        }
    }

    // gate: g_NA and out[] produced by node_kernel (index loads already in flight)
#if __CUDA_ARCH__ >= 900
    cudaGridDependencySynchronize();
#endif

#pragma unroll
    for (int stage = 0; stage < 3; stage++) {
        const bool valid = (stage == 0) ? vA : (stage == 1 ? vB : vC);
        if (!valid) break;
        const int j0 = (stage == 0) ? jA0 : (stage == 1 ? jB0 : jC0);
        const int j1 = (stage == 0) ? jA1 : (stage == 1 ? jB1 : jC1);
        const int i0 = (stage == 0) ? iA0 : (stage == 1 ? iB0 : iC0);
        const int i1 = (stage == 0) ? iA1 : (stage == 1 ? iB1 : iC1);

        // ---- issue all gathers up front (L1-resident table + ea) ----
        float4 Nj0 = __ldg(&g_NA[j0]);
        float4 Ni0 = __ldg(&g_NA[i0]);
        float4 Nj1 = __ldg(&g_NA[j1]);
        float4 Ni1 = __ldg(&g_NA[i1]);
        float  ea0 = __ldg(&edge_attr[(j0 % NUM_ATOMS) * NUM_ATOMS + (i0 % NUM_ATOMS)]);
        float  ea1 = __ldg(&edge_attr[(j1 % NUM_ATOMS) * NUM_ATOMS + (i1 % NUM_ATOMS)]);

#pragma unroll
        for (int k = 0; k < 2; k++) {
            float4 Ni = k ? Ni1 : Ni0;
            float4 Nj = k ? Nj1 : Nj0;
            float  ea = k ? ea1 : ea0;
            int    ii = k ? i1  : i0;

            float xi = Ni.x, ai = Ni.y;
            float xj = Nj.x, bj = Nj.z;
            unsigned ui = __float_as_uint(Ni.w);
            unsigned uj = __float_as_uint(Nj.w);
            float2 sci = __half22float2(*reinterpret_cast<__half2*>(&ui));
            float2 scj = __half22float2(*reinterpret_cast<__half2*>(&uj));
            float si = sci.x, ci = sci.y;
            float sj = scj.x, cj = scj.y;

            float d  = xj - xi;
            float sm = xj + xi;

            // trig of d and s via angle-sum identities
            float p1 = sj * ci, p2 = cj * si, p3 = ci * cj, p4 = si * sj;
            float sind = p1 - p2, sins = p1 + p2;
            float cosd = p3 + p4, coss = p3 - p4;

            float invd = safe_inv_f(d);
            float invs = safe_inv_f(sm);

            // activations via per-edge exp; tanh(z) = 2/(1+e^{-2z}) - 1
            float vd  = __expf(-d);
            float vs  = __expf(-sm);
            float vd2 = vd * vd, vs2 = vs * vs;
            float thd = fmaf(2.0f, __frcp_rn(1.0f + vd2), -1.0f);
            float sgd = __frcp_rn(1.0f + vd);
            float ths = fmaf(2.0f, __frcp_rn(1.0f + vs2), -1.0f);
            float sgs = __frcp_rn(1.0f + vs);

            float core = ai + bj;
            core = fmaf(wd1,  d,            core);
            core = fmaf(wd2,  d * d,        core);
            core = fmaf(wid,  invd,         core);
            core = fmaf(wid2, invd * invd,  core);
            core = fmaf(wis,  invs,         core);
            core = fmaf(wis2, invs * invs,  core);
            core = fmaf(wsd,  sind,         core);
            core = fmaf(wcd,  cosd,         core);
            core = fmaf(wss,  sins,         core);
            core = fmaf(wcs,  coss,         core);
            core = fmaf(wxx,  xi * xj,      core);
            core = fmaf(wxsj, xi * sj,      core);
            core = fmaf(wxsi, xj * si,      core);
            core = fmaf(wsdcs, sind * coss, core);
            core = fmaf(wthd, thd,          core);
            core = fmaf(wsgd, sgd,          core);
            core = fmaf(wrld, fmaxf(d, 0.0f),  core);
            core = fmaf(wths, ths,          core);
            core = fmaf(wsgs, sgs,          core);
            core = fmaf(wrls, fmaxf(sm, 0.0f), core);

            atomicAdd(&out[ii], ea * core);   // segment_sum over dst
        }
    }
}

extern "C" void kernel_launch(void* const* d_in, const int* in_sizes, int n_in,
                              void* d_out, int out_size) {
    // Identify inputs by element count (robust to whether scalar `t` occupies
    // a slot). Reference order: t?, x[10000], edge_index[2000000], c_mask[38],
    // f_mask[12], wc_2[76], wf_2[24], edge_attr_all[10000].
    const float* x   = nullptr;
    const void*  ei  = nullptr;
    const float* cm  = nullptr;
    const float* fm  = nullptr;
    const float* wc2 = nullptr;
    const float* wf2 = nullptr;
    const float* ea  = nullptr;
    for (int idx = 0; idx < n_in; idx++) {
        int s = in_sizes[idx];
        if (s == 2 * N_EDGES)      ei  = d_in[idx];
        else if (s == NCL)         cm  = (const float*)d_in[idx];
        else if (s == NFL)         fm  = (const float*)d_in[idx];
        else if (s == 2 * NCL)     wc2 = (const float*)d_in[idx];
        else if (s == 2 * NFL)     wf2 = (const float*)d_in[idx];
        else if (s == N_TOTAL) {
            if (!x) x = (const float*)d_in[idx];   // x comes first
            else    ea = (const float*)d_in[idx];  // edge_attr_all second
        }
    }
    float* out = (float*)d_out;

    node_kernel<<<(N_TOTAL + 255) / 256, 256>>>(x, cm, fm, wc2, wf2, out);

    // edge_kernel with programmatic dependent launch: prologue + ALL index loads
    // overlap node_kernel tail; cudaGridDependencySynchronize() gates g_NA/out.
    cudaLaunchConfig_t cfg = {};
    cfg.gridDim  = dim3(EDGE_BLOCKS, 1, 1);
    cfg.blockDim = dim3(EDGE_THREADS, 1, 1);
    cfg.dynamicSmemBytes = 0;
    cfg.stream = 0;
    cudaLaunchAttribute attr[1];
    attr[0].id = cudaLaunchAttributeProgrammaticStreamSerialization;
    attr[0].val.programmaticStreamSerializationAllowed = 1;
    cfg.attrs = attr;
    cfg.numAttrs = 1;
    cudaError_t err = cudaLaunchKernelEx(&cfg, edge_kernel, ei, cm, wc2,
                                         (const float*)ea, out);
    if (err != cudaSuccess) {
        // fallback: plain launch (still correct, just serialized)
        edge_kernel<<<EDGE_BLOCKS, EDGE_THREADS>>>(ei, cm, wc2, ea, out);
    }
}

// round 13
// speedup vs baseline: 1.0400x; 1.0271x over previous
#include <cuda_runtime.h>
#include <cuda_fp16.h>

// Problem constants (fixed by the dataset)
#define N_TOTAL   10000
#define NUM_ATOMS 100
#define N_EDGES   1000000
#define NCL 38
#define NFL 12

#define EDGE_BLOCKS  888          // 6 per SM
#define EDGE_THREADS 256
#define EPT 2
#define EDGE_CHUNK   1128         // 888 * 1128 = 1,001,664 >= 1e6; even

// Scratch (alloc-free rule: __device__ globals)
__device__ float4 g_NA[N_TOTAL];   // {x, a(i-role), b(j-role), half2(sin,cos)}

__device__ __forceinline__ float safe_inv_f(float v) {
    float w = (fabsf(v) < 0.01f) ? ((v >= 0.0f) ? 0.01f : -0.01f) : v;
    return __fdividef(1.0f, w);
}

// ---------------- node pass: F(x) -> out, plus packed per-node table ----------------
__global__ void node_kernel(const float* __restrict__ x,
                            const float* __restrict__ c_mask,
                            const float* __restrict__ f_mask,
                            const float* __restrict__ wc2,
                            const float* __restrict__ wf2,
                            float* __restrict__ out) {
    __shared__ float swc[NCL];
    __shared__ float swf[NFL];
    int t = threadIdx.x;
    if (t < NCL) swc[t] = c_mask[t] * (wc2[t] - wc2[t + NCL]);
    if (t < NFL) swf[t] = f_mask[t] * (wf2[t] - wf2[t + NFL]);
    __syncthreads();

    int n = blockIdx.x * blockDim.x + t;
    if (n >= N_TOTAL) return;
    float xv = x[n];
    float s, c;
    __sincosf(xv, &s, &c);
    float E = __expf(-xv);
    float R = __expf(xv);
    float inv  = safe_inv_f(xv);
    float inv2 = inv * inv;
    float th = (R - E) * __fdividef(1.0f, R + E);     // tanh(x)
    float sg = __fdividef(1.0f, 1.0f + E);            // sigmoid(x)
    float rl = fmaxf(xv, 0.0f);
    float x2 = xv * xv;

    float F = swf[0]
            + swf[1]*s + swf[2]*c + swf[3]*xv*s
            + swf[4]*xv + swf[5]*x2
            + swf[6]*inv + swf[7]*inv2 + swf[8]*inv2*inv
            + swf[9]*th + swf[10]*sg + swf[11]*rl;
    out[n] = F;   // F_COEF = 1; edge kernel accumulates on top

    // node-as-x_i contribution (feature idx 0,3,6,10,18,19,26,27,28)
    float a = swc[0]*xv + swc[3]*x2 + swc[6]*inv + swc[10]*inv2
            + swc[18]*s + swc[19]*c + swc[26]*th + swc[27]*sg + swc[28]*rl;
    // node-as-x_j contribution (feature idx 1,4,7,11,20,21,29,30,31)
    float b = swc[1]*xv + swc[4]*x2 + swc[7]*inv + swc[11]*inv2
            + swc[20]*s + swc[21]*c + swc[29]*th + swc[30]*sg + swc[31]*rl;

    __half2 sc = __floats2half2_rn(s, c);
    g_NA[n] = make_float4(xv, a, b, __uint_as_float(*reinterpret_cast<unsigned*>(&sc)));
}

// ---------------- edge pass: all-L1 gathers + atomics; PDL-gated ----------------
__global__ void __launch_bounds__(EDGE_THREADS, 6)
edge_kernel(const void* __restrict__ eidx_raw,
            const float* __restrict__ c_mask,
            const float* __restrict__ wc2,
            const float* __restrict__ edge_attr,
            float* __restrict__ out) {
    __shared__ float sW[NCL];
    __shared__ int   sE64;

    const int t = threadIdx.x;

    // -------- prologue: runs concurrently with node_kernel tail (PDL) --------
    if (t < NCL) sW[t] = c_mask[t] * (wc2[t] - wc2[t + NCL]);
    if (t >= 64 && t < 96) {
        int k = t - 64;
        const long long* p = (const long long*)eidx_raw;
        long long v0 = p[k];
        long long v1 = p[k + 32];
        int ok = (v0 >= 0 && v0 < N_TOTAL && v1 >= 0 && v1 < N_TOTAL) ? 1 : 0;
        unsigned m = __ballot_sync(0xFFFFFFFFu, ok);
        if (k == 0) sE64 = (m == 0xFFFFFFFFu) ? 1 : 0;
    }
    __syncthreads();

    const float wd1  = sW[2],  wd2  = sW[5];
    const float wid  = sW[8],  wis  = sW[9],  wid2 = sW[12], wis2 = sW[13];
    const float wsd  = sW[14], wcd  = sW[15], wss  = sW[16], wcs  = sW[17];
    const float wxx  = sW[22], wxsj = sW[23], wxsi = sW[24], wsdcs = sW[25];
    const float wthd = sW[32], wsgd = sW[33], wrld = sW[34];
    const float wths = sW[35], wsgs = sW[36], wrls = sW[37];
    const int e64 = sE64;

    // gate: g_NA and out[] produced by node_kernel
#if __CUDA_ARCH__ >= 900
    cudaGridDependencySynchronize();
#endif

    int start = blockIdx.x * EDGE_CHUNK;
    int end   = min(start + EDGE_CHUNK, N_EDGES);

    for (int e0 = start + (t << 1); e0 < end; e0 += (EDGE_THREADS << 1)) {
        // start/end even -> both edges of the pair always valid
        int js[EPT], is[EPT];
        if (e64) {
            const long long* e = (const long long*)eidx_raw;
            longlong2 s0 = __ldcs(reinterpret_cast<const longlong2*>(e + e0));
            longlong2 d0 = __ldcs(reinterpret_cast<const longlong2*>(e + N_EDGES + e0));
            js[0] = (int)s0.x; js[1] = (int)s0.y;
            is[0] = (int)d0.x; is[1] = (int)d0.y;
        } else {
            const int* e = (const int*)eidx_raw;
            int2 sp = __ldcs(reinterpret_cast<const int2*>(e + e0));
            int2 dp = __ldcs(reinterpret_cast<const int2*>(e + N_EDGES + e0));
            js[0] = sp.x; js[1] = sp.y;
            is[0] = dp.x; is[1] = dp.y;
        }

        // ---- issue all gathers up front (L1-resident table + ea) ----
        float4 Nj[EPT], Ni[EPT];
        float  ea[EPT];
#pragma unroll
        for (int k = 0; k < EPT; k++) {
            Nj[k] = __ldg(&g_NA[js[k]]);
            Ni[k] = __ldg(&g_NA[is[k]]);
        }
#pragma unroll
        for (int k = 0; k < EPT; k++)
            ea[k] = __ldg(&edge_attr[(js[k] % NUM_ATOMS) * NUM_ATOMS + (is[k] % NUM_ATOMS)]);

#pragma unroll
        for (int k = 0; k < EPT; k++) {
            float xi = Ni[k].x, ai = Ni[k].y;
            float xj = Nj[k].x, bj = Nj[k].z;
            unsigned ui = __float_as_uint(Ni[k].w);
            unsigned uj = __float_as_uint(Nj[k].w);
            float2 sci = __half22float2(*reinterpret_cast<__half2*>(&ui));
            float2 scj = __half22float2(*reinterpret_cast<__half2*>(&uj));
            float si = sci.x, ci = sci.y;
            float sj = scj.x, cj = scj.y;

            float d  = xj - xi;
            float sm = xj + xi;

            // trig of d and s via angle-sum identities
            float p1 = sj * ci, p2 = cj * si, p3 = ci * cj, p4 = si * sj;
            float sind = p1 - p2, sins = p1 + p2;
            float cosd = p3 + p4, coss = p3 - p4;

            float invd = safe_inv_f(d);
            float invs = safe_inv_f(sm);

            // activations of d and s via per-edge exp (MUFU is cheap)
            float vd  = __expf(-d);
            float vs  = __expf(-sm);
            float vd2 = vd * vd, vs2 = vs * vs;
            float thd = (1.0f - vd2) * __fdividef(1.0f, 1.0f + vd2);
            float sgd = __fdividef(1.0f, 1.0f + vd);
            float ths = (1.0f - vs2) * __fdividef(1.0f, 1.0f + vs2);
            float sgs = __fdividef(1.0f, 1.0f + vs);

            float core = ai + bj;
            core = fmaf(wd1,  d,            core);
            core = fmaf(wd2,  d * d,        core);
            core = fmaf(wid,  invd,         core);
            core = fmaf(wid2, invd * invd,  core);
            core = fmaf(wis,  invs,         core);
            core = fmaf(wis2, invs * invs,  core);
            core = fmaf(wsd,  sind,         core);
            core = fmaf(wcd,  cosd,         core);
            core = fmaf(wss,  sins,         core);
            core = fmaf(wcs,  coss,         core);
            core = fmaf(wxx,  xi * xj,      core);
            core = fmaf(wxsj, xi * sj,      core);
            core = fmaf(wxsi, xj * si,      core);
            core = fmaf(wsdcs, sind * coss, core);
            core = fmaf(wthd, thd,          core);
            core = fmaf(wsgd, sgd,          core);
            core = fmaf(wrld, fmaxf(d, 0.0f),  core);
            core = fmaf(wths, ths,          core);
            core = fmaf(wsgs, sgs,          core);
            core = fmaf(wrls, fmaxf(sm, 0.0f), core);

            atomicAdd(&out[is[k]], ea[k] * core);   // segment_sum over dst
        }
    }
}

extern "C" void kernel_launch(void* const* d_in, const int* in_sizes, int n_in,
                              void* d_out, int out_size) {
    // Identify inputs by element count (robust to whether scalar `t` occupies
    // a slot). Reference order: t?, x[10000], edge_index[2000000], c_mask[38],
    // f_mask[12], wc_2[76], wf_2[24], edge_attr_all[10000].
    const float* x   = nullptr;
    const void*  ei  = nullptr;
    const float* cm  = nullptr;
    const float* fm  = nullptr;
    const float* wc2 = nullptr;
    const float* wf2 = nullptr;
    const float* ea  = nullptr;
    for (int idx = 0; idx < n_in; idx++) {
        int s = in_sizes[idx];
        if (s == 2 * N_EDGES)      ei  = d_in[idx];
        else if (s == NCL)         cm  = (const float*)d_in[idx];
        else if (s == NFL)         fm  = (const float*)d_in[idx];
        else if (s == 2 * NCL)     wc2 = (const float*)d_in[idx];
        else if (s == 2 * NFL)     wf2 = (const float*)d_in[idx];
        else if (s == N_TOTAL) {
            if (!x) x = (const float*)d_in[idx];   // x comes first
            else    ea = (const float*)d_in[idx];  // edge_attr_all second
        }
    }
    float* out = (float*)d_out;

    node_kernel<<<(N_TOTAL + 255) / 256, 256>>>(x, cm, fm, wc2, wf2, out);

    // edge_kernel with programmatic dependent launch: prologue overlaps
    // node_kernel tail; cudaGridDependencySynchronize() gates g_NA/out use.
    cudaLaunchConfig_t cfg = {};
    cfg.gridDim  = dim3(EDGE_BLOCKS, 1, 1);
    cfg.blockDim = dim3(EDGE_THREADS, 1, 1);
    cfg.dynamicSmemBytes = 0;
    cfg.stream = 0;
    cudaLaunchAttribute attr[1];
    attr[0].id = cudaLaunchAttributeProgrammaticStreamSerialization;
    attr[0].val.programmaticStreamSerializationAllowed = 1;
    cfg.attrs = attr;
    cfg.numAttrs = 1;
    cudaError_t err = cudaLaunchKernelEx(&cfg, edge_kernel, ei, cm, wc2,
                                         (const float*)ea, out);
    if (err != cudaSuccess) {
        // fallback: plain launch (still correct, just serialized)
        edge_kernel<<<EDGE_BLOCKS, EDGE_THREADS>>>(ei, cm, wc2, ea, out);
    }
}

// round 14
// speedup vs baseline: 1.1115x; 1.0687x over previous
#include <cuda_runtime.h>
#include <cuda_fp16.h>

// Problem constants (fixed by the dataset)
#define N_TOTAL   10000
#define NUM_ATOMS 100
#define N_EDGES   1000000
#define NCL 38
#define NFL 12

#define EDGE_BLOCKS  888          // 6 per SM
#define EDGE_THREADS 256
#define EPT 2
#define EDGE_CHUNK   1128         // 888 * 1128 = 1,001,664 >= 1e6; even

// Scratch (alloc-free rule: __device__ globals)
__device__ float4 g_NA[N_TOTAL];   // {x, a(i-role), b(j-role), half2(sin,cos)}

__device__ __forceinline__ float safe_inv_f(float v) {
    float w = (fabsf(v) < 0.01f) ? ((v >= 0.0f) ? 0.01f : -0.01f) : v;
    return __fdividef(1.0f, w);
}

// ---------------- node pass: F(x) -> out, plus packed per-node table ----------------
__global__ void node_kernel(const float* __restrict__ x,
                            const float* __restrict__ c_mask,
                            const float* __restrict__ f_mask,
                            const float* __restrict__ wc2,
                            const float* __restrict__ wf2,
                            float* __restrict__ out) {
    __shared__ float swc[NCL];
    __shared__ float swf[NFL];
    int t = threadIdx.x;
    if (t < NCL) swc[t] = c_mask[t] * (wc2[t] - wc2[t + NCL]);
    if (t < NFL) swf[t] = f_mask[t] * (wf2[t] - wf2[t + NFL]);
    __syncthreads();

    int n = blockIdx.x * blockDim.x + t;
    if (n >= N_TOTAL) return;
    float xv = x[n];
    float s, c;
    __sincosf(xv, &s, &c);
    float E = __expf(-xv);
    float R = __expf(xv);
    float inv  = safe_inv_f(xv);
    float inv2 = inv * inv;
    float th = (R - E) * __fdividef(1.0f, R + E);     // tanh(x)
    float sg = __fdividef(1.0f, 1.0f + E);            // sigmoid(x)
    float rl = fmaxf(xv, 0.0f);
    float x2 = xv * xv;

    float F = swf[0]
            + swf[1]*s + swf[2]*c + swf[3]*xv*s
            + swf[4]*xv + swf[5]*x2
            + swf[6]*inv + swf[7]*inv2 + swf[8]*inv2*inv
            + swf[9]*th + swf[10]*sg + swf[11]*rl;
    out[n] = F;   // F_COEF = 1; edge kernel accumulates on top

    // node-as-x_i contribution (feature idx 0,3,6,10,18,19,26,27,28)
    float a = swc[0]*xv + swc[3]*x2 + swc[6]*inv + swc[10]*inv2
            + swc[18]*s + swc[19]*c + swc[26]*th + swc[27]*sg + swc[28]*rl;
    // node-as-x_j contribution (feature idx 1,4,7,11,20,21,29,30,31)
    float b = swc[1]*xv + swc[4]*x2 + swc[7]*inv + swc[11]*inv2
            + swc[20]*s + swc[21]*c + swc[29]*th + swc[30]*sg + swc[31]*rl;

    __half2 sc = __floats2half2_rn(s, c);
    g_NA[n] = make_float4(xv, a, b, __uint_as_float(*reinterpret_cast<unsigned*>(&sc)));
}

// ---------------- edge pass: all-L1 gathers + atomics; PDL-gated ----------------
__global__ void __launch_bounds__(EDGE_THREADS, 6)
edge_kernel(const void* __restrict__ eidx_raw,
            const float* __restrict__ c_mask,
            const float* __restrict__ wc2,
            const float* __restrict__ edge_attr,
            float* __restrict__ out) {
    __shared__ float sW[NCL];
    __shared__ int   sE64;

    const int t = threadIdx.x;

    // -------- prologue: runs concurrently with node_kernel tail (PDL) --------
    if (t < NCL) sW[t] = c_mask[t] * (wc2[t] - wc2[t + NCL]);
    if (t >= 64 && t < 96) {
        int k = t - 64;
        const long long* p = (const long long*)eidx_raw;
        long long v0 = p[k];
        long long v1 = p[k + 32];
        int ok = (v0 >= 0 && v0 < N_TOTAL && v1 >= 0 && v1 < N_TOTAL) ? 1 : 0;
        unsigned m = __ballot_sync(0xFFFFFFFFu, ok);
        if (k == 0) sE64 = (m == 0xFFFFFFFFu) ? 1 : 0;
    }
    __syncthreads();

    const float wd1  = sW[2],  wd2  = sW[5];
    const float wid  = sW[8],  wis  = sW[9],  wid2 = sW[12], wis2 = sW[13];
    const float wsd  = sW[14], wcd  = sW[15], wss  = sW[16], wcs  = sW[17];
    const float wxx  = sW[22], wxsj = sW[23], wxsi = sW[24], wsdcs = sW[25];
    const float wthd = sW[32], wsgd = sW[33], wrld = sW[34];
    const float wths = sW[35], wsgs = sW[36], wrls = sW[37];
    const int e64 = sE64;

    // gate: g_NA and out[] produced by node_kernel
#if __CUDA_ARCH__ >= 900
    cudaGridDependencySynchronize();
#endif

    int start = blockIdx.x * EDGE_CHUNK;
    int end   = min(start + EDGE_CHUNK, N_EDGES);

    for (int e0 = start + (t << 1); e0 < end; e0 += (EDGE_THREADS << 1)) {
        // start/end even -> both edges of the pair always valid
        int js[EPT], is[EPT];
        if (e64) {
            const long long* e = (const long long*)eidx_raw;
            longlong2 s0 = __ldcs(reinterpret_cast<const longlong2*>(e + e0));
            longlong2 d0 = __ldcs(reinterpret_cast<const longlong2*>(e + N_EDGES + e0));
            js[0] = (int)s0.x; js[1] = (int)s0.y;
            is[0] = (int)d0.x; is[1] = (int)d0.y;
        } else {
            const int* e = (const int*)eidx_raw;
            int2 sp = __ldcs(reinterpret_cast<const int2*>(e + e0));
            int2 dp = __ldcs(reinterpret_cast<const int2*>(e + N_EDGES + e0));
            js[0] = sp.x; js[1] = sp.y;
            is[0] = dp.x; is[1] = dp.y;
        }

        // ---- issue all gathers up front (L1-resident table + ea) ----
        float4 Nj[EPT], Ni[EPT];
        float  ea[EPT];
#pragma unroll
        for (int k = 0; k < EPT; k++) {
            Nj[k] = __ldg(&g_NA[js[k]]);
            Ni[k] = __ldg(&g_NA[is[k]]);
        }
#pragma unroll
        for (int k = 0; k < EPT; k++)
            ea[k] = __ldg(&edge_attr[(js[k] % NUM_ATOMS) * NUM_ATOMS + (is[k] % NUM_ATOMS)]);

#pragma unroll
        for (int k = 0; k < EPT; k++) {
            float xi = Ni[k].x, ai = Ni[k].y;
            float xj = Nj[k].x, bj = Nj[k].z;
            unsigned ui = __float_as_uint(Ni[k].w);
            unsigned uj = __float_as_uint(Nj[k].w);
            float2 sci = __half22float2(*reinterpret_cast<__half2*>(&ui));
            float2 scj = __half22float2(*reinterpret_cast<__half2*>(&uj));
            float si = sci.x, ci = sci.y;
            float sj = scj.x, cj = scj.y;

            float d  = xj - xi;
            float sm = xj + xi;

            // trig of d and s via angle-sum identities
            float p1 = sj * ci, p2 = cj * si, p3 = ci * cj, p4 = si * sj;
            float sind = p1 - p2, sins = p1 + p2;
            float cosd = p3 + p4, coss = p3 - p4;

            float invd = safe_inv_f(d);
            float invs = safe_inv_f(sm);

            // activations of d and s via per-edge exp (MUFU is cheap)
            float vd  = __expf(-d);
            float vs  = __expf(-sm);
            float vd2 = vd * vd, vs2 = vs * vs;
            float thd = (1.0f - vd2) * __fdividef(1.0f, 1.0f + vd2);
            float sgd = __fdividef(1.0f, 1.0f + vd);
            float ths = (1.0f - vs2) * __fdividef(1.0f, 1.0f + vs2);
            float sgs = __fdividef(1.0f, 1.0f + vs);

            float core = ai + bj;
            core = fmaf(wd1,  d,            core);
            core = fmaf(wd2,  d * d,        core);
            core = fmaf(wid,  invd,         core);
            core = fmaf(wid2, invd * invd,  core);
            core = fmaf(wis,  invs,         core);
            core = fmaf(wis2, invs * invs,  core);
            core = fmaf(wsd,  sind,         core);
            core = fmaf(wcd,  cosd,         core);
            core = fmaf(wss,  sins,         core);
            core = fmaf(wcs,  coss,         core);
            core = fmaf(wxx,  xi * xj,      core);
            core = fmaf(wxsj, xi * sj,      core);
            core = fmaf(wxsi, xj * si,      core);
            core = fmaf(wsdcs, sind * coss, core);
            core = fmaf(wthd, thd,          core);
            core = fmaf(wsgd, sgd,          core);
            core = fmaf(wrld, fmaxf(d, 0.0f),  core);
            core = fmaf(wths, ths,          core);
            core = fmaf(wsgs, sgs,          core);
            core = fmaf(wrls, fmaxf(sm, 0.0f), core);

            atomicAdd(&out[is[k]], ea[k] * core);   // segment_sum over dst
        }
    }
}

extern "C" void kernel_launch(void* const* d_in, const int* in_sizes, int n_in,
                              void* d_out, int out_size) {
    // Identify inputs by element count (robust to whether scalar `t` occupies
    // a slot). Reference order: t?, x[10000], edge_index[2000000], c_mask[38],
    // f_mask[12], wc_2[76], wf_2[24], edge_attr_all[10000].
    const float* x   = nullptr;
    const void*  ei  = nullptr;
    const float* cm  = nullptr;
    const float* fm  = nullptr;
    const float* wc2 = nullptr;
    const float* wf2 = nullptr;
    const float* ea  = nullptr;
    for (int idx = 0; idx < n_in; idx++) {
        int s = in_sizes[idx];
        if (s == 2 * N_EDGES)      ei  = d_in[idx];
        else if (s == NCL)         cm  = (const float*)d_in[idx];
        else if (s == NFL)         fm  = (const float*)d_in[idx];
        else if (s == 2 * NCL)     wc2 = (const float*)d_in[idx];
        else if (s == 2 * NFL)     wf2 = (const float*)d_in[idx];
        else if (s == N_TOTAL) {
            if (!x) x = (const float*)d_in[idx];   // x comes first
            else    ea = (const float*)d_in[idx];  // edge_attr_all second
        }
    }
    float* out = (float*)d_out;

    node_kernel<<<(N_TOTAL + 255) / 256, 256>>>(x, cm, fm, wc2, wf2, out);

    // edge_kernel with programmatic dependent launch: prologue overlaps
    // node_kernel tail; cudaGridDependencySynchronize() gates g_NA/out use.
    cudaLaunchConfig_t cfg = {};
    cfg.gridDim  = dim3(EDGE_BLOCKS, 1, 1);
    cfg.blockDim = dim3(EDGE_THREADS, 1, 1);
    cfg.dynamicSmemBytes = 0;
    cfg.stream = 0;
    cudaLaunchAttribute attr[1];
    attr[0].id = cudaLaunchAttributeProgrammaticStreamSerialization;
    attr[0].val.programmaticStreamSerializationAllowed = 1;
    cfg.attrs = attr;
    cfg.numAttrs = 1;
    cudaError_t err = cudaLaunchKernelEx(&cfg, edge_kernel, ei, cm, wc2,
                                         (const float*)ea, out);
    if (err != cudaSuccess) {
        // fallback: plain launch (still correct, just serialized)
        edge_kernel<<<EDGE_BLOCKS, EDGE_THREADS>>>(ei, cm, wc2, ea, out);
    }
}